// round 1
// baseline (speedup 1.0000x reference)
#include <cuda_runtime.h>
#include <cuda_bf16.h>

#define BB   16384
#define DD   64
#define NTT  128
#define NZC  2048

// ---- scratch (allocation-free: __device__ globals) ----
__device__ float g_phi_t[NTT];
__device__ float g_WzT[NZC * DD];   // Wz transposed: [j][d]
__device__ float g_bias[DD];
__device__ float g_q[NZC];
__device__ float g_cn[NZC];         // ||centres_z[j]||^2
__device__ float g_inv[NZC];        // exp(-2*log_sigmas_z[j])

// ---- stage 0: phi_t (128 values) ----
__global__ void k_phi_t(const float* __restrict__ t,
                        const float* __restrict__ ct,
                        const float* __restrict__ lst) {
    int i = threadIdx.x;
    if (i < NTT) {
        float r = fabsf(t[0] - ct[i]) / __expf(lst[i]);
        g_phi_t[i] = __expf(-r * r);
    }
}

// ---- stage 1: W_t = einsum('dij,i->dj'); store transposed + bias ----
// One thread per (d, j) output; consecutive threads over j -> coalesced W reads.
__global__ void k_wt(const float* __restrict__ W) {
    __shared__ float sphi[NTT];
    for (int i = threadIdx.x; i < NTT; i += blockDim.x) sphi[i] = g_phi_t[i];
    __syncthreads();

    int idx = blockIdx.x * blockDim.x + threadIdx.x;
    if (idx >= DD * (NZC + 1)) return;
    int d = idx / (NZC + 1);
    int j = idx - d * (NZC + 1);

    const float* wp = W + (size_t)d * NTT * (NZC + 1) + j;
    float s = 0.f;
#pragma unroll 8
    for (int i = 0; i < NTT; i++)
        s = fmaf(sphi[i], wp[(size_t)i * (NZC + 1)], s);

    if (j < NZC) g_WzT[j * DD + d] = s;
    else         g_bias[d] = s;
}

// ---- stage 2: per-centre constants: q[j], ||c_j||^2, inv_s2[j] ----
__global__ void k_prep(const float* __restrict__ cz,
                       const float* __restrict__ lsz) {
    int j = blockIdx.x * blockDim.x + threadIdx.x;
    if (j >= NZC) return;
    const float* c = cz + j * DD;
    const float* w = g_WzT + j * DD;
    float q = 0.f, cn = 0.f;
#pragma unroll
    for (int d = 0; d < DD; d++) {
        float cv = c[d];
        q  = fmaf(w[d], cv, q);
        cn = fmaf(cv,  cv, cn);
    }
    g_q[j]   = q;
    g_cn[j]  = cn;
    g_inv[j] = __expf(-2.f * lsz[j]);
}

// ---- stage 3: main fused kernel. One thread = one batch row. ----
__global__ void __launch_bounds__(128)
k_main(const float* __restrict__ z,
       const float* __restrict__ cz,
       float* __restrict__ out) {
    int b = blockIdx.x * 128 + threadIdx.x;

    // z row + squared norm in registers
    const float4* z4 = reinterpret_cast<const float4*>(z + (size_t)b * DD);
    float4 zr[16];
    float zn = 0.f;
#pragma unroll
    for (int k = 0; k < 16; k++) {
        float4 v = z4[k];
        zr[k] = v;
        zn = fmaf(v.x, v.x, zn); zn = fmaf(v.y, v.y, zn);
        zn = fmaf(v.z, v.z, zn); zn = fmaf(v.w, v.w, zn);
    }

    float4 acc[16];
#pragma unroll
    for (int k = 0; k < 16; k++) acc[k] = make_float4(0.f, 0.f, 0.f, 0.f);
    float tr = 0.f;

    const float4* czAll = reinterpret_cast<const float4*>(cz);
    const float4* wAll  = reinterpret_cast<const float4*>(g_WzT);

    for (int j = 0; j < NZC; j++) {
        const float4* c4 = czAll + j * 16;
        const float4* w4 = wAll  + j * 16;

        float dc = 0.f, dw = 0.f;
        float4 wv[16];
#pragma unroll
        for (int k = 0; k < 16; k++) {
            float4 c = __ldg(&c4[k]);
            float4 w = __ldg(&w4[k]);
            wv[k] = w;
            dc = fmaf(zr[k].x, c.x, dc); dc = fmaf(zr[k].y, c.y, dc);
            dc = fmaf(zr[k].z, c.z, dc); dc = fmaf(zr[k].w, c.w, dc);
            dw = fmaf(zr[k].x, w.x, dw); dw = fmaf(zr[k].y, w.y, dw);
            dw = fmaf(zr[k].z, w.z, dw); dw = fmaf(zr[k].w, w.w, dw);
        }

        float inv = g_inv[j];
        float sq  = fmaxf(fmaf(-2.f, dc, zn + g_cn[j]), 0.f);
        float phi = __expf(-sq * inv);
        tr = fmaf(phi * inv, dw - g_q[j], tr);

#pragma unroll
        for (int k = 0; k < 16; k++) {
            acc[k].x = fmaf(phi, wv[k].x, acc[k].x);
            acc[k].y = fmaf(phi, wv[k].y, acc[k].y);
            acc[k].z = fmaf(phi, wv[k].z, acc[k].z);
            acc[k].w = fmaf(phi, wv[k].w, acc[k].w);
        }
    }

    // dz_dt = acc + bias  -> out[0 : B*D)
    float4* o4 = reinterpret_cast<float4*>(out + (size_t)b * DD);
    const float4* b4 = reinterpret_cast<const float4*>(g_bias);
#pragma unroll
    for (int k = 0; k < 16; k++) {
        float4 bv = b4[k];
        o4[k] = make_float4(acc[k].x + bv.x, acc[k].y + bv.y,
                            acc[k].z + bv.z, acc[k].w + bv.w);
    }
    // dlogp_z_dt = -trace = +2 * tr  -> out[B*D + b]
    out[(size_t)BB * DD + b] = 2.f * tr;
}

extern "C" void kernel_launch(void* const* d_in, const int* in_sizes, int n_in,
                              void* d_out, int out_size) {
    const float* t   = (const float*)d_in[0];
    const float* z   = (const float*)d_in[1];
    // d_in[2] = logp_z (unused)
    const float* cz  = (const float*)d_in[3];
    const float* lsz = (const float*)d_in[4];
    const float* ct  = (const float*)d_in[5];
    const float* lst = (const float*)d_in[6];
    const float* W   = (const float*)d_in[7];
    float* out = (float*)d_out;

    k_phi_t<<<1, 128>>>(t, ct, lst);

    int nwt = DD * (NZC + 1);
    k_wt<<<(nwt + 255) / 256, 256>>>(W);

    k_prep<<<(NZC + 127) / 128, 128>>>(cz, lsz);

    k_main<<<BB / 128, 128>>>(z, cz, out);
}

// round 2
// speedup vs baseline: 6.2433x; 6.2433x over previous
#include <cuda_runtime.h>
#include <cuda_bf16.h>

#define BB   16384
#define DD   64
#define NTT  128
#define NZC  2048
#define JS   8            // j-splits (grid.y)
#define JPB  (NZC / JS)   // 256 j per block
#define TJ   16           // j-tile staged in smem

// ---- scratch (allocation-free: __device__ globals) ----
__device__ float g_phi_t[NTT];
__device__ float g_WzT[NZC * DD];           // Wz transposed: [j][d]
__device__ float g_bias[DD];
__device__ float g_q[NZC];
__device__ float g_cn[NZC];
__device__ float g_inv[NZC];
__device__ float g_pdz[JS * 16 * BB * 4];   // partial dz: [split][k(=d/4)][b] float4
__device__ float g_ptr[JS * BB];            // partial trace

// ---- packed f32x2 helpers ----
__device__ __forceinline__ unsigned long long ffma2(unsigned long long a,
                                                    unsigned long long b,
                                                    unsigned long long c) {
    unsigned long long d;
    asm("fma.rn.f32x2 %0, %1, %2, %3;" : "=l"(d) : "l"(a), "l"(b), "l"(c));
    return d;
}
__device__ __forceinline__ unsigned long long fadd2(unsigned long long a,
                                                    unsigned long long b) {
    unsigned long long d;
    asm("add.rn.f32x2 %0, %1, %2;" : "=l"(d) : "l"(a), "l"(b));
    return d;
}
__device__ __forceinline__ float hsum2(unsigned long long a) {
    float lo, hi;
    asm("mov.b64 {%0, %1}, %2;" : "=f"(lo), "=f"(hi) : "l"(a));
    return lo + hi;
}
__device__ __forceinline__ unsigned long long pack2(float lo, float hi) {
    unsigned long long d;
    asm("mov.b64 %0, {%1, %2};" : "=l"(d) : "f"(lo), "f"(hi));
    return d;
}
__device__ __forceinline__ void unpack2(unsigned long long a, float& lo, float& hi) {
    asm("mov.b64 {%0, %1}, %2;" : "=f"(lo), "=f"(hi) : "l"(a));
}

// ---- stage 0: phi_t ----
__global__ void k_phi_t(const float* __restrict__ t,
                        const float* __restrict__ ct,
                        const float* __restrict__ lst) {
    int i = threadIdx.x;
    if (i < NTT) {
        float r = fabsf(t[0] - ct[i]) / __expf(lst[i]);
        g_phi_t[i] = __expf(-r * r);
    }
}

// ---- stage 1: W_t = einsum('dij,i->dj'); store transposed + bias ----
__global__ void k_wt(const float* __restrict__ W) {
    __shared__ float sphi[NTT];
    for (int i = threadIdx.x; i < NTT; i += blockDim.x) sphi[i] = g_phi_t[i];
    __syncthreads();

    int idx = blockIdx.x * blockDim.x + threadIdx.x;
    if (idx >= DD * (NZC + 1)) return;
    int d = idx / (NZC + 1);
    int j = idx - d * (NZC + 1);

    const float* wp = W + (size_t)d * NTT * (NZC + 1) + j;
    float s = 0.f;
#pragma unroll 8
    for (int i = 0; i < NTT; i++)
        s = fmaf(sphi[i], wp[(size_t)i * (NZC + 1)], s);

    if (j < NZC) g_WzT[j * DD + d] = s;
    else         g_bias[d] = s;
}

// ---- stage 2: per-centre constants ----
__global__ void k_prep(const float* __restrict__ cz,
                       const float* __restrict__ lsz) {
    int j = blockIdx.x * blockDim.x + threadIdx.x;
    if (j >= NZC) return;
    const float* c = cz + j * DD;
    const float* w = g_WzT + j * DD;
    float q = 0.f, cn = 0.f;
#pragma unroll
    for (int d = 0; d < DD; d++) {
        float cv = c[d];
        q  = fmaf(w[d], cv, q);
        cn = fmaf(cv,  cv, cn);
    }
    g_q[j]   = q;
    g_cn[j]  = cn;
    g_inv[j] = __expf(-2.f * lsz[j]);
}

// ---- stage 3: main fused kernel. thread = row, block.y = j-split ----
__global__ void __launch_bounds__(128)
k_main(const float* __restrict__ z,
       const float* __restrict__ cz) {
    const int b     = blockIdx.x * 128 + threadIdx.x;
    const int split = blockIdx.y;
    const int jbase = split * JPB;
    const int tid   = threadIdx.x;

    __shared__ float4 sbuf[TJ * 32];   // [jj][0..15]=c float4, [16..31]=w float4
    __shared__ float  sinv[TJ], scn[TJ], sqq[TJ];

    // z row packed as f32x2 pairs (z2[m] = dims 2m,2m+1); zn = ||z||^2
    const ulonglong2* zu = reinterpret_cast<const ulonglong2*>(z + (size_t)b * DD);
    unsigned long long z2[32];
    float zn = 0.f;
#pragma unroll
    for (int k = 0; k < 16; k++) {
        ulonglong2 u = zu[k];
        z2[2 * k]     = u.x;
        z2[2 * k + 1] = u.y;
        float a0, a1, b0, b1;
        unpack2(u.x, a0, a1);
        unpack2(u.y, b0, b1);
        zn = fmaf(a0, a0, zn); zn = fmaf(a1, a1, zn);
        zn = fmaf(b0, b0, zn); zn = fmaf(b1, b1, zn);
    }

    unsigned long long acc[32];   // acc[m] accumulates dims (2m, 2m+1)
#pragma unroll
    for (int k = 0; k < 32; k++) acc[k] = 0ull;
    float tr = 0.f;

    const float4* cz4 = reinterpret_cast<const float4*>(cz);
    const float4* wz4 = reinterpret_cast<const float4*>(g_WzT);

    for (int tile = 0; tile < JPB / TJ; tile++) {
        const int jt = jbase + tile * TJ;
        __syncthreads();
#pragma unroll
        for (int it = 0; it < 4; it++) {
            int q  = tid + it * 128;
            int jj = q >> 5;
            int w  = q & 31;
            sbuf[q] = (w < 16) ? cz4[(jt + jj) * 16 + w]
                               : wz4[(jt + jj) * 16 + (w - 16)];
        }
        if (tid < TJ) {
            sinv[tid] = g_inv[jt + tid];
            scn[tid]  = g_cn[jt + tid];
            sqq[tid]  = g_q[jt + tid];
        }
        __syncthreads();

#pragma unroll 2
        for (int jj = 0; jj < TJ; jj++) {
            // each row is 64 floats = 16 ulonglong2 = 32 packed f32x2 halves
            const ulonglong2* c2 =
                reinterpret_cast<const ulonglong2*>(&sbuf[jj * 32]);       // 8 u2 = 32 floats? no: float4==16B==ulonglong2; 16 float4 -> 16 u2
            const ulonglong2* w2 =
                reinterpret_cast<const ulonglong2*>(&sbuf[jj * 32 + 16]);

            unsigned long long dc0 = 0ull, dc1 = 0ull, dw0 = 0ull, dw1 = 0ull;
            unsigned long long wv[32];   // wv[m] = dims (2m, 2m+1)
#pragma unroll
            for (int k = 0; k < 16; k++) {
                ulonglong2 cv = c2[k];           // dims 4k..4k+3
                dc0 = ffma2(z2[2 * k],     cv.x, dc0);
                dc1 = ffma2(z2[2 * k + 1], cv.y, dc1);
                ulonglong2 wvv = w2[k];
                wv[2 * k]     = wvv.x;
                wv[2 * k + 1] = wvv.y;
                dw0 = ffma2(z2[2 * k],     wvv.x, dw0);
                dw1 = ffma2(z2[2 * k + 1], wvv.y, dw1);
            }
            float dc  = hsum2(fadd2(dc0, dc1));
            float dw  = hsum2(fadd2(dw0, dw1));
            float inv = sinv[jj];
            float sq  = fmaxf(fmaf(-2.f, dc, zn + scn[jj]), 0.f);
            float phi = __expf(-sq * inv);
            tr = fmaf(phi * inv, dw - sqq[jj], tr);
            unsigned long long phi2 = pack2(phi, phi);
#pragma unroll
            for (int k = 0; k < 32; k++)
                acc[k] = ffma2(phi2, wv[k], acc[k]);
        }
    }

    // write partials: [split][k][b] float4, k = d/4
    float4* pd = reinterpret_cast<float4*>(g_pdz);
#pragma unroll
    for (int k = 0; k < 16; k++) {
        float4 f;
        unpack2(acc[2 * k],     f.x, f.y);
        unpack2(acc[2 * k + 1], f.z, f.w);
        pd[(split * 16 + k) * BB + b] = f;
    }
    g_ptr[split * BB + b] = tr;
}

// ---- stage 4a: reduce dz partials + bias ----
__global__ void k_reduce(float* __restrict__ out) {
    int gid = blockIdx.x * 256 + threadIdx.x;   // BB*16 threads
    if (gid >= BB * 16) return;
    int k = gid >> 14;          // / BB
    int b = gid & (BB - 1);
    const float4* pd    = reinterpret_cast<const float4*>(g_pdz);
    const float4* bias4 = reinterpret_cast<const float4*>(g_bias);
    float4 s = bias4[k];
#pragma unroll
    for (int sp = 0; sp < JS; sp++) {
        float4 p = pd[(sp * 16 + k) * BB + b];
        s.x += p.x; s.y += p.y; s.z += p.z; s.w += p.w;
    }
    reinterpret_cast<float4*>(out)[b * 16 + k] = s;
}

// ---- stage 4b: reduce trace partials ----
__global__ void k_reduce_tr(float* __restrict__ out) {
    int b = blockIdx.x * 256 + threadIdx.x;
    if (b >= BB) return;
    float s = 0.f;
#pragma unroll
    for (int sp = 0; sp < JS; sp++) s += g_ptr[sp * BB + b];
    out[(size_t)BB * DD + b] = 2.f * s;
}

extern "C" void kernel_launch(void* const* d_in, const int* in_sizes, int n_in,
                              void* d_out, int out_size) {
    const float* t   = (const float*)d_in[0];
    const float* z   = (const float*)d_in[1];
    const float* cz  = (const float*)d_in[3];
    const float* lsz = (const float*)d_in[4];
    const float* ct  = (const float*)d_in[5];
    const float* lst = (const float*)d_in[6];
    const float* W   = (const float*)d_in[7];
    float* out = (float*)d_out;

    k_phi_t<<<1, 128>>>(t, ct, lst);

    int nwt = DD * (NZC + 1);
    k_wt<<<(nwt + 255) / 256, 256>>>(W);

    k_prep<<<(NZC + 127) / 128, 128>>>(cz, lsz);

    dim3 g(BB / 128, JS);
    k_main<<<g, 128>>>(z, cz);

    k_reduce<<<(BB * 16 + 255) / 256, 256>>>(out);
    k_reduce_tr<<<(BB + 255) / 256, 256>>>(out);
}

// round 6
// speedup vs baseline: 14.8310x; 2.3755x over previous
#include <cuda_runtime.h>
#include <cuda_bf16.h>
#include <cstdint>

#define BB   16384
#define DD   64
#define NTT  128
#define NZC  2048
#define MT   128            // rows per CTA
#define NT   32             // j per chunk
#define NCH  (NZC / NT)     // 64

// ---------------- device scratch (no allocations) ----------------
__device__ float g_phi_t[NTT];
__device__ float g_WzT[NZC * DD];     // f32 [j][d] (for q)
__device__ float g_bias[DD];
__device__ float g_q[NZC];
__device__ float g_cn[NZC];
__device__ float g_inv[NZC];
__device__ float g_zn[BB];
__device__ __nv_bfloat16 g_czh[NZC * DD], g_czl[NZC * DD];   // centres [j][d]
__device__ __nv_bfloat16 g_wzh[NZC * DD], g_wzl[NZC * DD];   // Wz [j][d]
__device__ __nv_bfloat16 g_wth[DD * NZC], g_wtl[DD * NZC];   // Wz^T [d][j] (j contiguous)

// ---------------- smem layout (per buffer, bytes) ----------------
#define CZROW 144                       // 128B data + 16B pad (16B-aligned rows)
#define WTROW 80                        // 64B data + 16B pad
#define CZH_OFF 0
#define CZL_OFF (CZH_OFF + 32 * CZROW)  // 4608
#define WZH_OFF (CZL_OFF + 32 * CZROW)  // 9216
#define WZL_OFF (WZH_OFF + 32 * CZROW)  // 13824
#define WTH_OFF (WZL_OFF + 32 * CZROW)  // 18432
#define WTL_OFF (WTH_OFF + 64 * WTROW)  // 23552
#define CN_OFF  (WTL_OFF + 64 * WTROW)  // 28672
#define Q_OFF   (CN_OFF + 128)
#define INV_OFF (Q_OFF + 128)
#define BUFSZ   (INV_OFF + 128)         // 29056
#define SMEM_TOTAL (2 * BUFSZ)          // 58112

// ---------------- helpers ----------------
__device__ __forceinline__ uint32_t smem_u32(const void* p) {
    uint32_t a;
    asm("{ .reg .u64 t; cvta.to.shared.u64 t, %1; cvt.u32.u64 %0, t; }"
        : "=r"(a) : "l"(p));
    return a;
}
__device__ __forceinline__ void cpa16(uint32_t dst, const void* src) {
    asm volatile("cp.async.cg.shared.global [%0], [%1], 16;"
                 :: "r"(dst), "l"(__cvta_generic_to_global(src)) : "memory");
}
#define CP_COMMIT() asm volatile("cp.async.commit_group;" ::: "memory")
#define CP_WAIT(n)  asm volatile("cp.async.wait_group %0;" :: "n"(n) : "memory")

__device__ __forceinline__ uint32_t lds32(uint32_t a) {
    uint32_t v; asm("ld.shared.b32 %0, [%1];" : "=r"(v) : "r"(a)); return v;
}
__device__ __forceinline__ float ldsf(uint32_t a) {
    float v; asm("ld.shared.f32 %0, [%1];" : "=f"(v) : "r"(a)); return v;
}

// mma.sync m16n8k16 row.col f32 += bf16*bf16
__device__ __forceinline__ void mma_bf16(float* d, const uint32_t* a,
                                         uint32_t b0, uint32_t b1) {
    asm volatile("mma.sync.aligned.m16n8k16.row.col.f32.bf16.bf16.f32 "
                 "{%0,%1,%2,%3}, {%4,%5,%6,%7}, {%8,%9}, {%0,%1,%2,%3};"
                 : "+f"(d[0]), "+f"(d[1]), "+f"(d[2]), "+f"(d[3])
                 : "r"(a[0]), "r"(a[1]), "r"(a[2]), "r"(a[3]), "r"(b0), "r"(b1));
}

// pack two f32 -> bf16x2 (x in low half), plus residual pair
__device__ __forceinline__ void split2(float x, float y, uint32_t& hi, uint32_t& lo) {
    uint32_t h;
    asm("cvt.rn.satfinite.bf16x2.f32 %0, %1, %2;" : "=r"(h) : "f"(y), "f"(x));
    float hx = __uint_as_float(h << 16);
    float hy = __uint_as_float(h & 0xFFFF0000u);
    float lx = x - hx, ly = y - hy;
    uint32_t l;
    asm("cvt.rn.satfinite.bf16x2.f32 %0, %1, %2;" : "=r"(l) : "f"(ly), "f"(lx));
    hi = h; lo = l;
}

// ---------------- prep kernels ----------------
__global__ void k_phi_t(const float* __restrict__ t, const float* __restrict__ ct,
                        const float* __restrict__ lst) {
    int i = threadIdx.x;
    if (i < NTT) {
        float r = fabsf(t[0] - ct[i]) / __expf(lst[i]);
        g_phi_t[i] = __expf(-r * r);
    }
}

__global__ void k_wt(const float* __restrict__ W) {
    __shared__ float sphi[NTT];
    for (int i = threadIdx.x; i < NTT; i += blockDim.x) sphi[i] = g_phi_t[i];
    __syncthreads();
    int idx = blockIdx.x * blockDim.x + threadIdx.x;
    if (idx >= DD * (NZC + 1)) return;
    int d = idx / (NZC + 1);
    int j = idx - d * (NZC + 1);
    const float* wp = W + (size_t)d * NTT * (NZC + 1) + j;
    float s = 0.f;
#pragma unroll 8
    for (int i = 0; i < NTT; i++) s = fmaf(sphi[i], wp[(size_t)i * (NZC + 1)], s);
    if (j < NZC) {
        g_WzT[j * DD + d] = s;
        __nv_bfloat16 h = __float2bfloat16(s);
        __nv_bfloat16 l = __float2bfloat16(s - __bfloat162float(h));
        g_wzh[j * DD + d] = h;  g_wzl[j * DD + d] = l;
        g_wth[d * NZC + j] = h; g_wtl[d * NZC + j] = l;
    } else {
        g_bias[d] = s;
    }
}

__global__ void k_prep(const float* __restrict__ cz, const float* __restrict__ lsz) {
    int j = blockIdx.x * blockDim.x + threadIdx.x;
    if (j >= NZC) return;
    const float* c = cz + j * DD;
    const float* w = g_WzT + j * DD;
    float q = 0.f, cn = 0.f;
#pragma unroll
    for (int d = 0; d < DD; d++) {
        float cv = c[d];
        q  = fmaf(w[d], cv, q);
        cn = fmaf(cv,  cv, cn);
    }
    g_q[j] = q; g_cn[j] = cn; g_inv[j] = __expf(-2.f * lsz[j]);
}

__global__ void k_cz(const float* __restrict__ cz) {
    int i = blockIdx.x * blockDim.x + threadIdx.x;
    if (i >= NZC * DD) return;
    float x = cz[i];
    __nv_bfloat16 h = __float2bfloat16(x);
    g_czh[i] = h;
    g_czl[i] = __float2bfloat16(x - __bfloat162float(h));
}

__global__ void k_zn(const float* __restrict__ z) {
    int b = blockIdx.x * blockDim.x + threadIdx.x;
    if (b >= BB) return;
    const float4* z4 = reinterpret_cast<const float4*>(z + (size_t)b * DD);
    float s = 0.f;
#pragma unroll
    for (int k = 0; k < 16; k++) {
        float4 v = z4[k];
        s = fmaf(v.x, v.x, s); s = fmaf(v.y, v.y, s);
        s = fmaf(v.z, v.z, s); s = fmaf(v.w, v.w, s);
    }
    g_zn[b] = s;
}

// ---------------- chunk staging (cp.async) ----------------
__device__ __forceinline__ void stage(uint32_t sb, int buf, int j0, int tid) {
    uint32_t base = sb + buf * BUFSZ;
    int j = tid >> 3, u = tid & 7;        // 32 rows x 8 segs of 16B
    cpa16(base + CZH_OFF + j * CZROW + u * 16, g_czh + (size_t)(j0 + j) * DD + u * 8);
    cpa16(base + CZL_OFF + j * CZROW + u * 16, g_czl + (size_t)(j0 + j) * DD + u * 8);
    cpa16(base + WZH_OFF + j * CZROW + u * 16, g_wzh + (size_t)(j0 + j) * DD + u * 8);
    cpa16(base + WZL_OFF + j * CZROW + u * 16, g_wzl + (size_t)(j0 + j) * DD + u * 8);
    int d = tid >> 2, v = tid & 3;        // 64 rows x 4 segs of 16B
    cpa16(base + WTH_OFF + d * WTROW + v * 16, g_wth + (size_t)d * NZC + j0 + v * 8);
    cpa16(base + WTL_OFF + d * WTROW + v * 16, g_wtl + (size_t)d * NZC + j0 + v * 8);
    if (tid < 8)       cpa16(base + CN_OFF  + tid * 16,        g_cn  + j0 + tid * 4);
    else if (tid < 16) cpa16(base + Q_OFF   + (tid - 8) * 16,  g_q   + j0 + (tid - 8) * 4);
    else if (tid < 24) cpa16(base + INV_OFF + (tid - 16) * 16, g_inv + j0 + (tid - 16) * 4);
}

// ---------------- main tensor kernel ----------------
__global__ void __launch_bounds__(256, 1)
k_main(const float* __restrict__ z, float* __restrict__ out) {
    extern __shared__ __align__(16) char smem[];
    uint32_t sb = smem_u32(smem);
    const int tid  = threadIdx.x;
    const int warp = tid >> 5, lane = tid & 31;
    const int g = lane >> 2, t = lane & 3;
    const int b0 = blockIdx.x * MT;
    const int row0 = warp * 16 + g;       // local row of c0/c1
    const int row1 = row0 + 8;            // local row of c2/c3

    // ---- z A-fragments (constant across all chunks), split bf16 ----
    uint32_t zah[4][4], zal[4][4];
#pragma unroll
    for (int ks = 0; ks < 4; ks++) {
#pragma unroll
        for (int i = 0; i < 4; i++) {
            int r = (i & 1) ? row1 : row0;
            int d = ks * 16 + ((i >> 1) ? 8 : 0) + 2 * t;
            float2 v = *reinterpret_cast<const float2*>(z + (size_t)(b0 + r) * DD + d);
            split2(v.x, v.y, zah[ks][i], zal[ks][i]);
        }
    }
    const float zn0 = g_zn[b0 + row0];
    const float zn1 = g_zn[b0 + row1];

    float dz[8][4];
#pragma unroll
    for (int i = 0; i < 8; i++)
#pragma unroll
        for (int k = 0; k < 4; k++) dz[i][k] = 0.f;
    float tr0 = 0.f, tr1 = 0.f;

    stage(sb, 0, 0, tid);
    CP_COMMIT();

    for (int jc = 0; jc < NCH; jc++) {
        const int buf = jc & 1;
        if (jc + 1 < NCH) {
            stage(sb, buf ^ 1, (jc + 1) * NT, tid);
            CP_COMMIT();
            CP_WAIT(1);
        } else {
            CP_WAIT(0);
        }
        __syncthreads();
        const uint32_t base = sb + buf * BUFSZ;

        // ---- GEMM1 (S = z @ cz^T) and GEMM2 (Dw = z @ Wz^T), split bf16 ----
        float s[4][4], dw[4][4];
#pragma unroll
        for (int nt = 0; nt < 4; nt++) {
#pragma unroll
            for (int k = 0; k < 4; k++) { s[nt][k] = 0.f; dw[nt][k] = 0.f; }
            const uint32_t ch = base + CZH_OFF + (nt * 8 + g) * CZROW + t * 4;
            const uint32_t cl = ch + (CZL_OFF - CZH_OFF);
            const uint32_t wh = base + WZH_OFF + (nt * 8 + g) * CZROW + t * 4;
            const uint32_t wl = wh + (WZL_OFF - WZH_OFF);
#pragma unroll
            for (int ks = 0; ks < 4; ks++) {
                uint32_t b0h = lds32(ch + ks * 32), b1h = lds32(ch + ks * 32 + 16);
                uint32_t b0l = lds32(cl + ks * 32), b1l = lds32(cl + ks * 32 + 16);
                mma_bf16(s[nt], zah[ks], b0h, b1h);
                mma_bf16(s[nt], zal[ks], b0h, b1h);
                mma_bf16(s[nt], zah[ks], b0l, b1l);
                uint32_t e0h = lds32(wh + ks * 32), e1h = lds32(wh + ks * 32 + 16);
                uint32_t e0l = lds32(wl + ks * 32), e1l = lds32(wl + ks * 32 + 16);
                mma_bf16(dw[nt], zah[ks], e0h, e1h);
                mma_bf16(dw[nt], zal[ks], e0h, e1h);
                mma_bf16(dw[nt], zah[ks], e0l, e1l);
            }
        }

        // ---- epilogue: phi, trace, pack phi as A-frags (split) ----
        uint32_t pah[2][4], pal[2][4];
#pragma unroll
        for (int nt = 0; nt < 4; nt++) {
            const int jc0 = nt * 8 + 2 * t, jc1 = jc0 + 1;
            const float cn0 = ldsf(base + CN_OFF  + jc0 * 4);
            const float cn1 = ldsf(base + CN_OFF  + jc1 * 4);
            const float q0  = ldsf(base + Q_OFF   + jc0 * 4);
            const float q1  = ldsf(base + Q_OFF   + jc1 * 4);
            const float i0  = ldsf(base + INV_OFF + jc0 * 4);
            const float i1  = ldsf(base + INV_OFF + jc1 * 4);

            float ph00 = __expf(-fmaxf(fmaf(-2.f, s[nt][0], zn0 + cn0), 0.f) * i0);
            float ph01 = __expf(-fmaxf(fmaf(-2.f, s[nt][1], zn0 + cn1), 0.f) * i1);
            float ph10 = __expf(-fmaxf(fmaf(-2.f, s[nt][2], zn1 + cn0), 0.f) * i0);
            float ph11 = __expf(-fmaxf(fmaf(-2.f, s[nt][3], zn1 + cn1), 0.f) * i1);

            tr0 = fmaf(ph00 * i0, dw[nt][0] - q0, tr0);
            tr0 = fmaf(ph01 * i1, dw[nt][1] - q1, tr0);
            tr1 = fmaf(ph10 * i0, dw[nt][2] - q0, tr1);
            tr1 = fmaf(ph11 * i1, dw[nt][3] - q1, tr1);

            uint32_t h01, l01, h23, l23;
            split2(ph00, ph01, h01, l01);
            split2(ph10, ph11, h23, l23);
            const int ks = nt >> 1, off = (nt & 1) * 2;
            pah[ks][0 + off] = h01;  pal[ks][0 + off] = l01;
            pah[ks][1 + off] = h23;  pal[ks][1 + off] = l23;
        }

        // ---- GEMM3: dz += phi @ Wz (B = Wz^T [d][j] pairs over j) ----
#pragma unroll
        for (int ks = 0; ks < 2; ks++) {
#pragma unroll
            for (int nt = 0; nt < 8; nt++) {
                const uint32_t wr = base + WTH_OFF + (nt * 8 + g) * WTROW + t * 4;
                uint32_t b0h = lds32(wr + ks * 32), b1h = lds32(wr + ks * 32 + 16);
                uint32_t b0l = lds32(wr + (WTL_OFF - WTH_OFF) + ks * 32);
                uint32_t b1l = lds32(wr + (WTL_OFF - WTH_OFF) + ks * 32 + 16);
                mma_bf16(dz[nt], pah[ks], b0h, b1h);
                mma_bf16(dz[nt], pal[ks], b0h, b1h);
                mma_bf16(dz[nt], pah[ks], b0l, b1l);
            }
        }
        __syncthreads();   // all reads of buf done before it is restaged
    }

    // ---- trace: reduce over the 4 lanes of each row-group ----
    tr0 += __shfl_xor_sync(0xffffffff, tr0, 1);
    tr0 += __shfl_xor_sync(0xffffffff, tr0, 2);
    tr1 += __shfl_xor_sync(0xffffffff, tr1, 1);
    tr1 += __shfl_xor_sync(0xffffffff, tr1, 2);
    if (t == 0) {
        out[(size_t)BB * DD + b0 + row0] = 2.f * tr0;
        out[(size_t)BB * DD + b0 + row1] = 2.f * tr1;
    }

    // ---- dz + bias -> out ----
#pragma unroll
    for (int nt = 0; nt < 8; nt++) {
        const int d0 = nt * 8 + 2 * t;
        const float bx = g_bias[d0], by = g_bias[d0 + 1];
        float2 v0 = make_float2(dz[nt][0] + bx, dz[nt][1] + by);
        float2 v1 = make_float2(dz[nt][2] + bx, dz[nt][3] + by);
        *reinterpret_cast<float2*>(out + (size_t)(b0 + row0) * DD + d0) = v0;
        *reinterpret_cast<float2*>(out + (size_t)(b0 + row1) * DD + d0) = v1;
    }
}

// ---------------- launcher ----------------
extern "C" void kernel_launch(void* const* d_in, const int* in_sizes, int n_in,
                              void* d_out, int out_size) {
    const float* t   = (const float*)d_in[0];
    const float* z   = (const float*)d_in[1];
    const float* cz  = (const float*)d_in[3];
    const float* lsz = (const float*)d_in[4];
    const float* ct  = (const float*)d_in[5];
    const float* lst = (const float*)d_in[6];
    const float* W   = (const float*)d_in[7];
    float* out = (float*)d_out;

    static bool attr_set = false;
    if (!attr_set) {
        cudaFuncSetAttribute(k_main, cudaFuncAttributeMaxDynamicSharedMemorySize,
                             SMEM_TOTAL);
        attr_set = true;
    }

    k_phi_t<<<1, 128>>>(t, ct, lst);
    k_wt<<<(DD * (NZC + 1) + 255) / 256, 256>>>(W);
    k_prep<<<(NZC + 127) / 128, 128>>>(cz, lsz);
    k_cz<<<(NZC * DD + 255) / 256, 256>>>(cz);
    k_zn<<<(BB + 255) / 256, 256>>>(z);
    k_main<<<BB / MT, 256, SMEM_TOTAL>>>(z, out);
}